// round 10
// baseline (speedup 1.0000x reference)
#include <cuda_runtime.h>
#include <cuda_fp16.h>
#include <cstdint>
#include <math.h>

#define BB 4
#define SS 4096
#define DD 256
#define HH 1024
// SCALE * log2(e): softmax computed in base-2 domain
#define SCL2E 0.25505654911f

// ---------------------------------------------------------------------------
// Scratch (__device__ globals; no cudaMalloc allowed)
// ---------------------------------------------------------------------------
__device__ __half g_xh[(size_t)BB * SS * DD];
__device__ float  g_a[(size_t)BB * SS * DD];
__device__ float  g_h[(size_t)BB * SS * DD];
__device__ __half g_hf[(size_t)BB * SS * DD];
__device__ __half g_f1f[(size_t)BB * SS * HH];
__device__ float  g_f2[(size_t)BB * SS * DD];
__device__ __half g_w1t[(size_t)HH * DD];            // W1^T [H,D] fp16
__device__ __half g_w2t[(size_t)DD * HH];            // W2^T [D,H] fp16

// ---------------------------------------------------------------------------
// Helpers (baseline PTX only: cp.async, ldmatrix, mma.sync)
// ---------------------------------------------------------------------------
__device__ __forceinline__ uint32_t smem_u32(const void* p) {
    uint32_t a;
    asm("{ .reg .u64 t; cvta.to.shared.u64 t, %1; cvt.u32.u64 %0, t; }" : "=r"(a) : "l"(p));
    return a;
}
__device__ __forceinline__ void cpa16(uint32_t d, const void* g) {
    asm volatile("cp.async.cg.shared.global [%0], [%1], 16;" :: "r"(d), "l"(g) : "memory");
}
__device__ __forceinline__ uint32_t swz(uint32_t off) { return off ^ ((off >> 3) & 0x70); }

// Swizzle for 512B rows (256 fp16)
__device__ __forceinline__ uint32_t SWX(int row, int c) {
    return (uint32_t)(row * 512 + ((c ^ (row & 7)) << 4));
}
// Swizzle for 128B rows (64 fp16) — P tile
__device__ __forceinline__ uint32_t PSWX(int row, int c) {
    return (uint32_t)(row * 128 + ((c ^ (row & 7)) << 4));
}
__device__ __forceinline__ float ex2f(float x) {
    float y;
    asm("ex2.approx.f32 %0, %1;" : "=f"(y) : "f"(x));
    return y;
}

__device__ __forceinline__ void ldsm4(uint32_t& r0, uint32_t& r1, uint32_t& r2, uint32_t& r3,
                                      uint32_t addr) {
    asm volatile("ldmatrix.sync.aligned.m8n8.x4.shared.b16 {%0,%1,%2,%3}, [%4];"
        : "=r"(r0), "=r"(r1), "=r"(r2), "=r"(r3) : "r"(addr));
}
__device__ __forceinline__ void ldsm4t(uint32_t& r0, uint32_t& r1, uint32_t& r2, uint32_t& r3,
                                       uint32_t addr) {
    asm volatile("ldmatrix.sync.aligned.m8n8.x4.trans.shared.b16 {%0,%1,%2,%3}, [%4];"
        : "=r"(r0), "=r"(r1), "=r"(r2), "=r"(r3) : "r"(addr));
}
__device__ __forceinline__ void mma_f16(float* d, uint32_t a0, uint32_t a1, uint32_t a2,
                                        uint32_t a3, uint32_t b0, uint32_t b1) {
    asm volatile("mma.sync.aligned.m16n8k16.row.col.f32.f16.f16.f32 "
        "{%0,%1,%2,%3}, {%4,%5,%6,%7}, {%8,%9}, {%0,%1,%2,%3};"
        : "+f"(d[0]), "+f"(d[1]), "+f"(d[2]), "+f"(d[3])
        : "r"(a0), "r"(a1), "r"(a2), "r"(a3), "r"(b0), "r"(b1));
}
__device__ __forceinline__ uint32_t packh(float a, float b) {
    __half2 h = __floats2half2_rn(a, b);
    return *(uint32_t*)&h;
}

// ---------------------------------------------------------------------------
// Flash attention, low-smem-traffic org:
//   CTA = 32 q-rows, 128 threads (4 warps), 2 CTAs/SM.
//   warp w: row-group (w>>1)*16, key-half (w&1)*32 for QK; col-half (w&1)*128 for PV.
//   QK partial scores -> stat exchange via smem -> P staged in smem (fp16) ->
//   col-split PV (each warp reads only half the V fragments).
// smem: Q 16K | K buf0 32K | K buf1 32K | P 4K | stats 0.5K  = 84.5K -> 2 CTAs/SM
// ---------------------------------------------------------------------------
#define FA_SMEM 86528

__global__ void __launch_bounds__(128, 2) flash_attn(
    const __half* __restrict__ xh, float* __restrict__ out)
{
    extern __shared__ char smem[];
    const uint32_t sb = smem_u32(smem);
    const int tid = threadIdx.x, wid = tid >> 5, lane = tid & 31;
    const int rowgrp = wid >> 1;          // 0/1 -> rows rowgrp*16..+15
    const int khalf  = wid & 1;           // QK keys khalf*32.. ; PV cols khalf*128..
    const int m0 = blockIdx.x * 32;
    const int bz = blockIdx.y;
    const __half* qp = xh + ((size_t)bz * SS + m0) * DD;
    const __half* kp_all = xh + (size_t)bz * SS * DD;

    const uint32_t QH = sb;                      // 16K
    const uint32_t KB = sb + 16384;              // 2 x 32K
    const uint32_t PT = sb + 81920;              // 4K
    float* mx_s = (float*)(smem + 86016 - (sb - sb));        // stats: max [2][32]
    float* sm_s = (float*)(smem + 86016 + 256);              // sums [2][32]
    // (use byte offsets into the dynamic smem array)
    mx_s = (float*)(smem + 81920 + 4096);
    sm_s = (float*)(smem + 81920 + 4096 + 256);

    // Load Q (32 rows x 512B)
    #pragma unroll
    for (int i = 0; i < 8; i++) {
        int j = tid + i * 128;
        int row = j >> 5, c = j & 31;
        cpa16(QH + SWX(row, c), qp + row * DD + c * 8);
    }
    asm volatile("cp.async.commit_group;" ::: "memory");

    auto load_kv = [&](int t) {
        const uint32_t b = KB + (t & 1) * 32768;
        const __half* kp = kp_all + (size_t)t * 64 * DD;
        #pragma unroll
        for (int i = 0; i < 16; i++) {
            int j = tid + i * 128;
            int row = j >> 5, c = j & 31;
            cpa16(b + SWX(row, c), kp + row * DD + c * 8);
        }
        asm volatile("cp.async.commit_group;" ::: "memory");
    };

    load_kv(0);

    float O[16][4];                      // 16 rows x 128 cols per warp
    #pragma unroll
    for (int n = 0; n < 16; n++)
        #pragma unroll
        for (int q = 0; q < 4; q++) O[n][q] = 0.0f;
    float m0r = -INFINITY, m1r = -INFINITY, l0 = 0.0f, l1 = 0.0f;

    const int qrow = rowgrp * 16 + (lane & 15);
    const int qc_h = lane >> 4;
    const int krow = ((lane >> 4) << 3) + (lane & 7);
    const int kc_h = (lane >> 3) & 1;
    const int vrow = ((lane >> 3) & 1) * 8 + (lane & 7);
    const int r0 = lane >> 2;            // local row within 16-row group (and +8)
    const int srow0 = rowgrp * 16 + r0;  // stats row index
    const int srow1 = srow0 + 8;

    const int T = SS / 64;   // 64 key-tiles
    for (int t = 0; t < T; t++) {
        asm volatile("cp.async.wait_group 0;" ::: "memory");
        __syncthreads();                     // B1: K(t) visible; PV(t-1) complete
        if (t + 1 < T) load_kv(t + 1);       // overwrites buf[(t+1)&1] = buf[(t-1)&1], free now
        const uint32_t KH = KB + (t & 1) * 32768;

        // ---- partial scores: S(rows rowgrp*16.., keys khalf*32..) ----
        float sa[4][4];
        #pragma unroll
        for (int j = 0; j < 4; j++)
            #pragma unroll
            for (int q = 0; q < 4; q++) sa[j][q] = 0.0f;

        #pragma unroll
        for (int s = 0; s < 16; s++) {
            uint32_t ah[4], bh[4][2];
            ldsm4(ah[0], ah[1], ah[2], ah[3], QH + SWX(qrow, 2 * s + qc_h));
            #pragma unroll
            for (int jj = 0; jj < 2; jj++) {
                uint32_t off = SWX(khalf * 32 + jj * 16 + krow, 2 * s + kc_h);
                ldsm4(bh[2 * jj][0], bh[2 * jj][1], bh[2 * jj + 1][0], bh[2 * jj + 1][1],
                      KH + off);
            }
            #pragma unroll
            for (int j = 0; j < 4; j++)
                mma_f16(sa[j], ah[0], ah[1], ah[2], ah[3], bh[j][0], bh[j][1]);
        }
        #pragma unroll
        for (int j = 0; j < 4; j++)
            #pragma unroll
            for (int q = 0; q < 4; q++) sa[j][q] *= SCL2E;

        // ---- partial row max over this key-half ----
        float mx0 = -INFINITY, mx1 = -INFINITY;
        #pragma unroll
        for (int j = 0; j < 4; j++) {
            mx0 = fmaxf(mx0, fmaxf(sa[j][0], sa[j][1]));
            mx1 = fmaxf(mx1, fmaxf(sa[j][2], sa[j][3]));
        }
        mx0 = fmaxf(mx0, __shfl_xor_sync(0xffffffffu, mx0, 1));
        mx0 = fmaxf(mx0, __shfl_xor_sync(0xffffffffu, mx0, 2));
        mx1 = fmaxf(mx1, __shfl_xor_sync(0xffffffffu, mx1, 1));
        mx1 = fmaxf(mx1, __shfl_xor_sync(0xffffffffu, mx1, 2));
        if ((lane & 3) == 0) {
            mx_s[khalf * 32 + srow0] = mx0;
            mx_s[khalf * 32 + srow1] = mx1;
        }
        __syncthreads();                     // B2: partial maxes visible

        // ---- combined max, exp, partial sums, stage P ----
        const float cm0 = fmaxf(mx_s[srow0], mx_s[32 + srow0]);
        const float cm1 = fmaxf(mx_s[srow1], mx_s[32 + srow1]);
        const float mn0 = fmaxf(m0r, cm0), mn1 = fmaxf(m1r, cm1);
        const float sc0 = ex2f(m0r - mn0), sc1 = ex2f(m1r - mn1);
        m0r = mn0; m1r = mn1;

        float ts0 = 0.0f, ts1 = 0.0f;
        #pragma unroll
        for (int j = 0; j < 4; j++) {
            sa[j][0] = ex2f(sa[j][0] - mn0);
            sa[j][1] = ex2f(sa[j][1] - mn0);
            sa[j][2] = ex2f(sa[j][2] - mn1);
            sa[j][3] = ex2f(sa[j][3] - mn1);
            ts0 += sa[j][0] + sa[j][1];
            ts1 += sa[j][2] + sa[j][3];
        }
        ts0 += __shfl_xor_sync(0xffffffffu, ts0, 1);
        ts0 += __shfl_xor_sync(0xffffffffu, ts0, 2);
        ts1 += __shfl_xor_sync(0xffffffffu, ts1, 1);
        ts1 += __shfl_xor_sync(0xffffffffu, ts1, 2);
        if ((lane & 3) == 0) {
            sm_s[khalf * 32 + srow0] = ts0;
            sm_s[khalf * 32 + srow1] = ts1;
        }
        // stage P: rows srow0/srow1, keys khalf*32 + j*8 + (lane&3)*2 (chunk khalf*4+j)
        {
            const int co = (lane & 3) * 4;
            #pragma unroll
            for (int j = 0; j < 4; j++) {
                const int ch = khalf * 4 + j;
                uint32_t a0 = PT + (uint32_t)((rowgrp * 16 + r0) * 128 +
                               ((ch ^ (r0 & 7)) << 4) + co);
                uint32_t a1 = PT + (uint32_t)((rowgrp * 16 + r0 + 8) * 128 +
                               ((ch ^ ((r0 + 8) & 7)) << 4) + co);
                uint32_t p0 = packh(sa[j][0], sa[j][1]);
                uint32_t p1 = packh(sa[j][2], sa[j][3]);
                asm volatile("st.shared.b32 [%0], %1;" :: "r"(a0), "r"(p0) : "memory");
                asm volatile("st.shared.b32 [%0], %1;" :: "r"(a1), "r"(p1) : "memory");
            }
        }
        __syncthreads();                     // B3: P + partial sums visible

        l0 = l0 * sc0 + sm_s[srow0] + sm_s[32 + srow0];
        l1 = l1 * sc1 + sm_s[srow1] + sm_s[32 + srow1];
        if (sc0 != 1.0f || sc1 != 1.0f) {
            #pragma unroll
            for (int n = 0; n < 16; n++) {
                O[n][0] *= sc0; O[n][1] *= sc0;
                O[n][2] *= sc1; O[n][3] *= sc1;
            }
        }

        // ---- PV: O(rows rowgrp*16.., cols khalf*128..) += P(all 64 keys) @ V ----
        #pragma unroll
        for (int ks = 0; ks < 4; ks++) {
            uint32_t pa[4];
            ldsm4(pa[0], pa[1], pa[2], pa[3],
                  PT + PSWX(rowgrp * 16 + (lane & 15), ks * 2 + (lane >> 4)));
            #pragma unroll
            for (int g = 0; g < 8; g++) {
                uint32_t v0, v1, v2, v3;
                ldsm4t(v0, v1, v2, v3,
                       KH + SWX(ks * 16 + vrow, 2 * (khalf * 8 + g) + (lane >> 4)));
                mma_f16(O[2 * g],     pa[0], pa[1], pa[2], pa[3], v0, v1);
                mma_f16(O[2 * g + 1], pa[0], pa[1], pa[2], pa[3], v2, v3);
            }
        }
    }

    // ---- epilogue: rows m0 + rowgrp*16 + {r0, r0+8}, cols khalf*128 + n*8 + cq ----
    const float i0 = 1.0f / l0, i1 = 1.0f / l1;
    float* op = out + ((size_t)bz * SS + m0 + rowgrp * 16) * DD + khalf * 128;
    const int cq = (lane & 3) * 2;
    #pragma unroll
    for (int n = 0; n < 16; n++) {
        int col = n * 8 + cq;
        *(float2*)(op + (size_t)r0 * DD + col)       = make_float2(O[n][0] * i0, O[n][1] * i0);
        *(float2*)(op + (size_t)(r0 + 8) * DD + col) = make_float2(O[n][2] * i1, O[n][3] * i1);
    }
}

// ---------------------------------------------------------------------------
// FFN GEMM (fp16, 1-term): C[M,N] = A[M,K] * B[N,K]^T
// MODE 2: Cf f16 = relu(acc + bias)      MODE 3: C fp32 = acc + bias
// Block 128x128, K-tile 64, 8 warps (2x4), double-buffered.
// ---------------------------------------------------------------------------
#define Bb 32768   // per-buffer: A 16K | B 16K
template <int MODE>
__global__ void __launch_bounds__(256, 1) gemm_ffn(
    const __half* __restrict__ A, const __half* __restrict__ B,
    float* __restrict__ C, __half* __restrict__ Cf,
    const float* __restrict__ bias, int M, int N, int K)
{
    extern __shared__ char smem[];
    const uint32_t sb = smem_u32(smem);
    const int tid = threadIdx.x, wid = tid >> 5, lane = tid & 31;
    const int m0 = blockIdx.y * 128, n0 = blockIdx.x * 128;

    const int wm = wid & 1;
    const int wn = wid >> 1;
    const int a_row = lane & 15, a_kh = lane >> 4;
    const int b_roff = ((lane >> 4) & 1) * 8 + (lane & 7), b_kh = (lane >> 3) & 1;

    float acc[4][4][4];
    #pragma unroll
    for (int i = 0; i < 4; i++)
        #pragma unroll
        for (int j = 0; j < 4; j++)
            #pragma unroll
            for (int q = 0; q < 4; q++) acc[i][j][q] = 0.0f;

    const int KT = K >> 6;

    auto load_tile = [&](int kt) {
        const uint32_t tb = sb + (kt & 1) * Bb;
        const int k0 = kt << 6;
        #pragma unroll
        for (int t = 0; t < 4; t++) {
            int id = tid + t * 256;
            int row = id >> 3, ch = id & 7;
            uint32_t so = swz((uint32_t)(row * 128 + ch * 16));
            cpa16(tb + so,         A + (size_t)(m0 + row) * K + k0 + ch * 8);
            cpa16(tb + 16384 + so, B + (size_t)(n0 + row) * K + k0 + ch * 8);
        }
        asm volatile("cp.async.commit_group;" ::: "memory");
    };

    load_tile(0);

    for (int kt = 0; kt < KT; kt++) {
        if (kt + 1 < KT) {
            load_tile(kt + 1);
            asm volatile("cp.async.wait_group 1;" ::: "memory");
        } else {
            asm volatile("cp.async.wait_group 0;" ::: "memory");
        }
        __syncthreads();

        const uint32_t tb = sb + (kt & 1) * Bb;
        #pragma unroll
        for (int s = 0; s < 4; s++) {
            uint32_t av[4][4];
            #pragma unroll
            for (int i = 0; i < 4; i++) {
                uint32_t off = swz((uint32_t)((wm * 64 + i * 16 + a_row) * 128 +
                                              (s * 2 + a_kh) * 16));
                ldsm4(av[i][0], av[i][1], av[i][2], av[i][3], tb + off);
            }
            uint32_t bv[4][2];
            #pragma unroll
            for (int jj = 0; jj < 2; jj++) {
                uint32_t off = swz((uint32_t)((wn * 32 + jj * 16 + b_roff) * 128 +
                                              (s * 2 + b_kh) * 16));
                ldsm4(bv[2 * jj][0], bv[2 * jj][1], bv[2 * jj + 1][0], bv[2 * jj + 1][1],
                      tb + 16384 + off);
            }
            #pragma unroll
            for (int i = 0; i < 4; i++)
                #pragma unroll
                for (int j = 0; j < 4; j++)
                    mma_f16(acc[i][j], av[i][0], av[i][1], av[i][2], av[i][3],
                            bv[j][0], bv[j][1]);
        }
        __syncthreads();
    }

    const int g = lane >> 2, cq = (lane & 3) * 2;
    #pragma unroll
    for (int i = 0; i < 4; i++) {
        #pragma unroll
        for (int j = 0; j < 4; j++) {
            const int row = m0 + wm * 64 + i * 16 + g;
            const int col = n0 + wn * 32 + j * 8 + cq;
            float v0 = acc[i][j][0], v1 = acc[i][j][1];
            float v2 = acc[i][j][2], v3 = acc[i][j][3];
            const float bv0 = bias[col], bv1 = bias[col + 1];
            v0 += bv0; v1 += bv1; v2 += bv0; v3 += bv1;
            size_t i0 = (size_t)row * N + col;
            size_t i1 = (size_t)(row + 8) * N + col;
            if (MODE == 2) {
                v0 = fmaxf(v0, 0.f); v1 = fmaxf(v1, 0.f);
                v2 = fmaxf(v2, 0.f); v3 = fmaxf(v3, 0.f);
                *(__half2*)(Cf + i0) = __floats2half2_rn(v0, v1);
                *(__half2*)(Cf + i1) = __floats2half2_rn(v2, v3);
            } else {
                *(float2*)(C + i0) = {v0, v1};
                *(float2*)(C + i1) = {v2, v3};
            }
        }
    }
}

// ---------------------------------------------------------------------------
// Elementwise / conversion kernels
// ---------------------------------------------------------------------------
__global__ void conv_f16(const float* __restrict__ in, __half* __restrict__ o, size_t n) {
    size_t i = ((size_t)blockIdx.x * blockDim.x + threadIdx.x) * 4;
    if (i < n) {
        float4 v = *(const float4*)(in + i);
        *(__half2*)(o + i)     = __floats2half2_rn(v.x, v.y);
        *(__half2*)(o + i + 2) = __floats2half2_rn(v.z, v.w);
    }
}

__global__ void transpose_f16(const float* __restrict__ in, __half* __restrict__ o,
                              int R, int C) {
    __shared__ float t[32][33];
    int c = blockIdx.x * 32 + threadIdx.x;
    #pragma unroll
    for (int i = 0; i < 4; i++) {
        int r = blockIdx.y * 32 + threadIdx.y + i * 8;
        if (r < R && c < C) t[threadIdx.y + i * 8][threadIdx.x] = in[(size_t)r * C + c];
    }
    __syncthreads();
    int rr = blockIdx.y * 32 + threadIdx.x;
    #pragma unroll
    for (int i = 0; i < 4; i++) {
        int cc = blockIdx.x * 32 + threadIdx.y + i * 8;
        if (rr < R && cc < C)
            o[(size_t)cc * R + rr] = __float2half_rn(t[threadIdx.x][threadIdx.y + i * 8]);
    }
}

__global__ void add_ln(const float* __restrict__ a, const float* __restrict__ r,
                       const float* __restrict__ g, const float* __restrict__ be,
                       float* __restrict__ out, __half* __restrict__ of) {
    const size_t row = blockIdx.x;
    const int t = threadIdx.x;
    const size_t idx = row * DD + t;
    const float v = a[idx] + r[idx];
    __shared__ float sm[8];

    float s = v;
    #pragma unroll
    for (int o = 16; o > 0; o >>= 1) s += __shfl_xor_sync(0xffffffffu, s, o);
    if ((t & 31) == 0) sm[t >> 5] = s;
    __syncthreads();
    if (t < 32) {
        float z = (t < 8) ? sm[t] : 0.f;
        #pragma unroll
        for (int o = 4; o > 0; o >>= 1) z += __shfl_xor_sync(0xffffffffu, z, o);
        if (t == 0) sm[0] = z;
    }
    __syncthreads();
    const float mean = sm[0] * (1.0f / 256.0f);
    __syncthreads();

    const float d = v - mean;
    float q = d * d;
    #pragma unroll
    for (int o = 16; o > 0; o >>= 1) q += __shfl_xor_sync(0xffffffffu, q, o);
    if ((t & 31) == 0) sm[t >> 5] = q;
    __syncthreads();
    if (t < 32) {
        float z = (t < 8) ? sm[t] : 0.f;
        #pragma unroll
        for (int o = 4; o > 0; o >>= 1) z += __shfl_xor_sync(0xffffffffu, z, o);
        if (t == 0) sm[0] = z;
    }
    __syncthreads();
    const float var = sm[0] * (1.0f / 256.0f);
    const float res = d * rsqrtf(var + 1e-5f) * g[t] + be[t];
    out[idx] = res;
    if (of) of[idx] = __float2half_rn(res);
}

// ---------------------------------------------------------------------------
// Launch
// ---------------------------------------------------------------------------
extern "C" void kernel_launch(void* const* d_in, const int* in_sizes, int n_in,
                              void* d_out, int out_size) {
    const float* x      = (const float*)d_in[0];
    const float* gamma1 = (const float*)d_in[1];
    const float* beta1  = (const float*)d_in[2];
    const float* W1     = (const float*)d_in[3];
    const float* b1     = (const float*)d_in[4];
    const float* W2     = (const float*)d_in[5];
    const float* b2     = (const float*)d_in[6];
    const float* gamma2 = (const float*)d_in[7];
    const float* beta2  = (const float*)d_in[8];
    float* out = (float*)d_out;

    float *a, *h, *f2;
    __half *xh, *hf, *f1f, *w1t, *w2t;
    cudaGetSymbolAddress((void**)&xh, g_xh);
    cudaGetSymbolAddress((void**)&a, g_a);
    cudaGetSymbolAddress((void**)&h, g_h);
    cudaGetSymbolAddress((void**)&hf, g_hf);
    cudaGetSymbolAddress((void**)&f1f, g_f1f);
    cudaGetSymbolAddress((void**)&f2, g_f2);
    cudaGetSymbolAddress((void**)&w1t, g_w1t);
    cudaGetSymbolAddress((void**)&w2t, g_w2t);

    const int SMEM = 2 * Bb;   // 65536
    cudaFuncSetAttribute(gemm_ffn<2>, cudaFuncAttributeMaxDynamicSharedMemorySize, SMEM);
    cudaFuncSetAttribute(gemm_ffn<3>, cudaFuncAttributeMaxDynamicSharedMemorySize, SMEM);
    cudaFuncSetAttribute(flash_attn, cudaFuncAttributeMaxDynamicSharedMemorySize, FA_SMEM);

    const int rows = BB * SS;

    // conversions
    conv_f16<<<(BB * SS * DD / 4 + 255) / 256, 256>>>(x, xh, (size_t)BB * SS * DD);
    transpose_f16<<<dim3(HH / 32, DD / 32), dim3(32, 8)>>>(W1, w1t, DD, HH);
    transpose_f16<<<dim3(DD / 32, HH / 32), dim3(32, 8)>>>(W2, w2t, HH, DD);

    // 1-3) fused attention: a = softmax(scale * x x^T) x
    flash_attn<<<dim3(SS / 32, BB), 128, FA_SMEM>>>(xh, a);

    // 4) h = LN(a + x), also emit h f16
    add_ln<<<rows, 256>>>(a, x, gamma1, beta1, h, hf);

    // 5) f1 = relu(h @ W1 + b1) -> f16
    gemm_ffn<2><<<dim3(HH / 128, rows / 128), 256, SMEM>>>(
        hf, w1t, nullptr, f1f, b1, rows, HH, DD);

    // 6) f2 = f1 @ W2 + b2
    gemm_ffn<3><<<dim3(DD / 128, rows / 128), 256, SMEM>>>(
        f1f, w2t, f2, nullptr, b2, rows, DD, HH);

    // 7) out = LN(f2 + h)
    add_ln<<<rows, 256>>>(f2, h, gamma2, beta2, out, nullptr);
}

// round 11
// speedup vs baseline: 1.1665x; 1.1665x over previous
#include <cuda_runtime.h>
#include <cuda_fp16.h>
#include <cstdint>
#include <math.h>

#define BB 4
#define SS 4096
#define DD 256
#define HH 1024
// SCALE * log2(e): softmax computed in base-2 domain
#define SCL2E 0.25505654911f

// ---------------------------------------------------------------------------
// Scratch (__device__ globals; no cudaMalloc allowed)
// ---------------------------------------------------------------------------
__device__ __half g_xh[(size_t)BB * SS * DD];
__device__ float  g_a[(size_t)BB * SS * DD];
__device__ float  g_h[(size_t)BB * SS * DD];
__device__ __half g_hf[(size_t)BB * SS * DD];
__device__ __half g_f1f[(size_t)BB * SS * HH];
__device__ float  g_f2[(size_t)BB * SS * DD];
__device__ __half g_w1t[(size_t)HH * DD];            // W1^T [H,D] fp16
__device__ __half g_w2t[(size_t)DD * HH];            // W2^T [D,H] fp16

// ---------------------------------------------------------------------------
// Helpers (baseline PTX only: cp.async, ldmatrix, mma.sync)
// ---------------------------------------------------------------------------
__device__ __forceinline__ uint32_t smem_u32(const void* p) {
    uint32_t a;
    asm("{ .reg .u64 t; cvta.to.shared.u64 t, %1; cvt.u32.u64 %0, t; }" : "=r"(a) : "l"(p));
    return a;
}
__device__ __forceinline__ void cpa16(uint32_t d, const void* g) {
    asm volatile("cp.async.cg.shared.global [%0], [%1], 16;" :: "r"(d), "l"(g) : "memory");
}
__device__ __forceinline__ uint32_t swz(uint32_t off) { return off ^ ((off >> 3) & 0x70); }

// Swizzle for 512B rows (256 fp16)
__device__ __forceinline__ uint32_t SWX(int row, int c) {
    return (uint32_t)(row * 512 + ((c ^ (row & 7)) << 4));
}
__device__ __forceinline__ float ex2f(float x) {
    float y;
    asm("ex2.approx.f32 %0, %1;" : "=f"(y) : "f"(x));
    return y;
}

__device__ __forceinline__ void ldsm4(uint32_t& r0, uint32_t& r1, uint32_t& r2, uint32_t& r3,
                                      uint32_t addr) {
    asm volatile("ldmatrix.sync.aligned.m8n8.x4.shared.b16 {%0,%1,%2,%3}, [%4];"
        : "=r"(r0), "=r"(r1), "=r"(r2), "=r"(r3) : "r"(addr));
}
__device__ __forceinline__ void ldsm4t(uint32_t& r0, uint32_t& r1, uint32_t& r2, uint32_t& r3,
                                       uint32_t addr) {
    asm volatile("ldmatrix.sync.aligned.m8n8.x4.trans.shared.b16 {%0,%1,%2,%3}, [%4];"
        : "=r"(r0), "=r"(r1), "=r"(r2), "=r"(r3) : "r"(addr));
}
__device__ __forceinline__ void mma_f16(float* d, uint32_t a0, uint32_t a1, uint32_t a2,
                                        uint32_t a3, uint32_t b0, uint32_t b1) {
    asm volatile("mma.sync.aligned.m16n8k16.row.col.f32.f16.f16.f32 "
        "{%0,%1,%2,%3}, {%4,%5,%6,%7}, {%8,%9}, {%0,%1,%2,%3};"
        : "+f"(d[0]), "+f"(d[1]), "+f"(d[2]), "+f"(d[3])
        : "r"(a0), "r"(a1), "r"(a2), "r"(a3), "r"(b0), "r"(b1));
}
__device__ __forceinline__ uint32_t packh(float a, float b) {
    __half2 h = __floats2half2_rn(a, b);
    return *(uint32_t*)&h;
}

// ---------------------------------------------------------------------------
// Flash attention (pure fp16 QK/PV, fp32 accum) — R8 known-best shape:
// CTA: 64 query rows, 128 threads (4 warps x 16 rows), 2 CTAs/SM.
// K-tile: 64 keys, double-buffered (prefetch before wait).
// smem: Q 32K | K buf0 32K | K buf1 32K = 96K.
// ---------------------------------------------------------------------------
#define FA_SMEM 98304

__global__ void __launch_bounds__(128, 2) flash_attn(
    const __half* __restrict__ xh, float* __restrict__ out)
{
    extern __shared__ char smem[];
    const uint32_t sb = smem_u32(smem);
    const int tid = threadIdx.x, wid = tid >> 5, lane = tid & 31;
    const int m0 = blockIdx.x * 64;
    const int bz = blockIdx.y;
    const __half* qp = xh + ((size_t)bz * SS + m0) * DD;
    const __half* kp_all = xh + (size_t)bz * SS * DD;
    const uint32_t QH = sb, KB = sb + 32768;

    // Load Q (64 rows x 512B)
    #pragma unroll
    for (int i = 0; i < 16; i++) {
        int j = tid + i * 128;
        int row = j >> 5, c = j & 31;
        cpa16(QH + SWX(row, c), qp + row * DD + c * 8);
    }
    asm volatile("cp.async.commit_group;" ::: "memory");

    auto load_kv = [&](int t) {
        const uint32_t b = KB + (t & 1) * 32768;
        const __half* kp = kp_all + (size_t)t * 64 * DD;
        #pragma unroll
        for (int i = 0; i < 16; i++) {
            int j = tid + i * 128;
            int row = j >> 5, c = j & 31;
            cpa16(b + SWX(row, c), kp + row * DD + c * 8);
        }
        asm volatile("cp.async.commit_group;" ::: "memory");
    };

    load_kv(0);

    float O[32][4];
    #pragma unroll
    for (int n = 0; n < 32; n++)
        #pragma unroll
        for (int q = 0; q < 4; q++) O[n][q] = 0.0f;
    float m0r = -INFINITY, m1r = -INFINITY, l0 = 0.0f, l1 = 0.0f;

    const int qrow = wid * 16 + (lane & 15);
    const int qc_h = lane >> 4;
    const int krow = ((lane >> 4) << 3) + (lane & 7);
    const int kc_h = (lane >> 3) & 1;
    const int vrow = ((lane >> 3) & 1) * 8 + (lane & 7);

    const int T = SS / 64;   // 64 key-tiles
    for (int t = 0; t < T; t++) {
        // Prefetch next K tile into the other buffer BEFORE waiting on this one.
        if (t + 1 < T) {
            load_kv(t + 1);
            asm volatile("cp.async.wait_group 1;" ::: "memory");
        } else {
            asm volatile("cp.async.wait_group 0;" ::: "memory");
        }
        __syncthreads();
        const uint32_t KH = KB + (t & 1) * 32768;

        // ---- S2 = (scale*log2e) * Q K^T  (log2-domain scores) ----
        float sa[8][4];
        #pragma unroll
        for (int j = 0; j < 8; j++)
            #pragma unroll
            for (int q = 0; q < 4; q++) sa[j][q] = 0.0f;

        #pragma unroll
        for (int s = 0; s < 16; s++) {
            uint32_t ah[4], bh[8][2];
            ldsm4(ah[0], ah[1], ah[2], ah[3], QH + SWX(qrow, 2 * s + qc_h));
            #pragma unroll
            for (int r4 = 0; r4 < 4; r4++) {
                uint32_t off = SWX(krow + 16 * r4, 2 * s + kc_h);
                ldsm4(bh[2 * r4][0], bh[2 * r4][1], bh[2 * r4 + 1][0], bh[2 * r4 + 1][1],
                      KH + off);
            }
            #pragma unroll
            for (int j = 0; j < 8; j++)
                mma_f16(sa[j], ah[0], ah[1], ah[2], ah[3], bh[j][0], bh[j][1]);
        }
        #pragma unroll
        for (int j = 0; j < 8; j++)
            #pragma unroll
            for (int q = 0; q < 4; q++) sa[j][q] *= SCL2E;

        // ---- online softmax in base-2 (rows lane>>2 and +8) ----
        float mx0 = -INFINITY, mx1 = -INFINITY;
        #pragma unroll
        for (int j = 0; j < 8; j++) {
            mx0 = fmaxf(mx0, fmaxf(sa[j][0], sa[j][1]));
            mx1 = fmaxf(mx1, fmaxf(sa[j][2], sa[j][3]));
        }
        mx0 = fmaxf(mx0, __shfl_xor_sync(0xffffffffu, mx0, 1));
        mx0 = fmaxf(mx0, __shfl_xor_sync(0xffffffffu, mx0, 2));
        mx1 = fmaxf(mx1, __shfl_xor_sync(0xffffffffu, mx1, 1));
        mx1 = fmaxf(mx1, __shfl_xor_sync(0xffffffffu, mx1, 2));
        float mn0 = fmaxf(m0r, mx0), mn1 = fmaxf(m1r, mx1);
        float sc0 = ex2f(m0r - mn0), sc1 = ex2f(m1r - mn1);
        m0r = mn0; m1r = mn1;

        float ts0 = 0.0f, ts1 = 0.0f;
        #pragma unroll
        for (int j = 0; j < 8; j++) {
            sa[j][0] = ex2f(sa[j][0] - mn0);
            sa[j][1] = ex2f(sa[j][1] - mn0);
            sa[j][2] = ex2f(sa[j][2] - mn1);
            sa[j][3] = ex2f(sa[j][3] - mn1);
            ts0 += sa[j][0] + sa[j][1];
            ts1 += sa[j][2] + sa[j][3];
        }
        ts0 += __shfl_xor_sync(0xffffffffu, ts0, 1);
        ts0 += __shfl_xor_sync(0xffffffffu, ts0, 2);
        ts1 += __shfl_xor_sync(0xffffffffu, ts1, 1);
        ts1 += __shfl_xor_sync(0xffffffffu, ts1, 2);
        l0 = l0 * sc0 + ts0;
        l1 = l1 * sc1 + ts1;
        if (sc0 != 1.0f || sc1 != 1.0f) {
            #pragma unroll
            for (int n = 0; n < 32; n++) {
                O[n][0] *= sc0; O[n][1] *= sc0;
                O[n][2] *= sc1; O[n][3] *= sc1;
            }
        }

        // ---- P fragments (fp16), 4 k16 chunks over 64 keys ----
        uint32_t pa[4][4];
        #pragma unroll
        for (int ks = 0; ks < 4; ks++) {
            int j0 = 2 * ks, j1 = 2 * ks + 1;
            pa[ks][0] = packh(sa[j0][0], sa[j0][1]);
            pa[ks][1] = packh(sa[j0][2], sa[j0][3]);
            pa[ks][2] = packh(sa[j1][0], sa[j1][1]);
            pa[ks][3] = packh(sa[j1][2], sa[j1][3]);
        }

        // ---- O += P @ V  (V = K tile via ldmatrix.trans) ----
        #pragma unroll
        for (int ks = 0; ks < 4; ks++) {
            #pragma unroll
            for (int g = 0; g < 16; g++) {
                uint32_t v0, v1, v2, v3;
                ldsm4t(v0, v1, v2, v3, KH + SWX(ks * 16 + vrow, 2 * g + (lane >> 4)));
                mma_f16(O[2 * g],     pa[ks][0], pa[ks][1], pa[ks][2], pa[ks][3], v0, v1);
                mma_f16(O[2 * g + 1], pa[ks][0], pa[ks][1], pa[ks][2], pa[ks][3], v2, v3);
            }
        }
        __syncthreads();
    }

    // ---- epilogue ----
    const float i0 = 1.0f / l0, i1 = 1.0f / l1;
    float* op = out + ((size_t)bz * SS + m0 + wid * 16) * DD;
    const int r0 = lane >> 2, cq = (lane & 3) * 2;
    #pragma unroll
    for (int n = 0; n < 32; n++) {
        int col = n * 8 + cq;
        *(float2*)(op + (size_t)r0 * DD + col)       = make_float2(O[n][0] * i0, O[n][1] * i0);
        *(float2*)(op + (size_t)(r0 + 8) * DD + col) = make_float2(O[n][2] * i1, O[n][3] * i1);
    }
}

// ---------------------------------------------------------------------------
// FFN GEMM (fp16, 1-term): C[M,N] = A[M,K] * B[N,K]^T
// MODE 2: Cf f16 = relu(acc + bias)      MODE 3: C fp32 = acc + bias
// Block 128x128, K-tile 64, 8 warps (2x4), double-buffered.
// ---------------------------------------------------------------------------
#define Bb 32768   // per-buffer: A 16K | B 16K
template <int MODE>
__global__ void __launch_bounds__(256, 1) gemm_ffn(
    const __half* __restrict__ A, const __half* __restrict__ B,
    float* __restrict__ C, __half* __restrict__ Cf,
    const float* __restrict__ bias, int M, int N, int K)
{
    extern __shared__ char smem[];
    const uint32_t sb = smem_u32(smem);
    const int tid = threadIdx.x, wid = tid >> 5, lane = tid & 31;
    const int m0 = blockIdx.y * 128, n0 = blockIdx.x * 128;

    const int wm = wid & 1;
    const int wn = wid >> 1;
    const int a_row = lane & 15, a_kh = lane >> 4;
    const int b_roff = ((lane >> 4) & 1) * 8 + (lane & 7), b_kh = (lane >> 3) & 1;

    float acc[4][4][4];
    #pragma unroll
    for (int i = 0; i < 4; i++)
        #pragma unroll
        for (int j = 0; j < 4; j++)
            #pragma unroll
            for (int q = 0; q < 4; q++) acc[i][j][q] = 0.0f;

    const int KT = K >> 6;

    auto load_tile = [&](int kt) {
        const uint32_t tb = sb + (kt & 1) * Bb;
        const int k0 = kt << 6;
        #pragma unroll
        for (int t = 0; t < 4; t++) {
            int id = tid + t * 256;
            int row = id >> 3, ch = id & 7;
            uint32_t so = swz((uint32_t)(row * 128 + ch * 16));
            cpa16(tb + so,         A + (size_t)(m0 + row) * K + k0 + ch * 8);
            cpa16(tb + 16384 + so, B + (size_t)(n0 + row) * K + k0 + ch * 8);
        }
        asm volatile("cp.async.commit_group;" ::: "memory");
    };

    load_tile(0);

    for (int kt = 0; kt < KT; kt++) {
        if (kt + 1 < KT) {
            load_tile(kt + 1);
            asm volatile("cp.async.wait_group 1;" ::: "memory");
        } else {
            asm volatile("cp.async.wait_group 0;" ::: "memory");
        }
        __syncthreads();

        const uint32_t tb = sb + (kt & 1) * Bb;
        #pragma unroll
        for (int s = 0; s < 4; s++) {
            uint32_t av[4][4];
            #pragma unroll
            for (int i = 0; i < 4; i++) {
                uint32_t off = swz((uint32_t)((wm * 64 + i * 16 + a_row) * 128 +
                                              (s * 2 + a_kh) * 16));
                ldsm4(av[i][0], av[i][1], av[i][2], av[i][3], tb + off);
            }
            uint32_t bv[4][2];
            #pragma unroll
            for (int jj = 0; jj < 2; jj++) {
                uint32_t off = swz((uint32_t)((wn * 32 + jj * 16 + b_roff) * 128 +
                                              (s * 2 + b_kh) * 16));
                ldsm4(bv[2 * jj][0], bv[2 * jj][1], bv[2 * jj + 1][0], bv[2 * jj + 1][1],
                      tb + 16384 + off);
            }
            #pragma unroll
            for (int i = 0; i < 4; i++)
                #pragma unroll
                for (int j = 0; j < 4; j++)
                    mma_f16(acc[i][j], av[i][0], av[i][1], av[i][2], av[i][3],
                            bv[j][0], bv[j][1]);
        }
        __syncthreads();
    }

    const int g = lane >> 2, cq = (lane & 3) * 2;
    #pragma unroll
    for (int i = 0; i < 4; i++) {
        #pragma unroll
        for (int j = 0; j < 4; j++) {
            const int row = m0 + wm * 64 + i * 16 + g;
            const int col = n0 + wn * 32 + j * 8 + cq;
            float v0 = acc[i][j][0], v1 = acc[i][j][1];
            float v2 = acc[i][j][2], v3 = acc[i][j][3];
            const float bv0 = bias[col], bv1 = bias[col + 1];
            v0 += bv0; v1 += bv1; v2 += bv0; v3 += bv1;
            size_t i0 = (size_t)row * N + col;
            size_t i1 = (size_t)(row + 8) * N + col;
            if (MODE == 2) {
                v0 = fmaxf(v0, 0.f); v1 = fmaxf(v1, 0.f);
                v2 = fmaxf(v2, 0.f); v3 = fmaxf(v3, 0.f);
                *(__half2*)(Cf + i0) = __floats2half2_rn(v0, v1);
                *(__half2*)(Cf + i1) = __floats2half2_rn(v2, v3);
            } else {
                *(float2*)(C + i0) = {v0, v1};
                *(float2*)(C + i1) = {v2, v3};
            }
        }
    }
}

// ---------------------------------------------------------------------------
// Elementwise / conversion kernels
// ---------------------------------------------------------------------------
__global__ void conv_f16(const float* __restrict__ in, __half* __restrict__ o, size_t n) {
    size_t i = ((size_t)blockIdx.x * blockDim.x + threadIdx.x) * 8;
    if (i < n) {
        float4 v0 = *(const float4*)(in + i);
        float4 v1 = *(const float4*)(in + i + 4);
        uint4 r;
        r.x = packh(v0.x, v0.y);
        r.y = packh(v0.z, v0.w);
        r.z = packh(v1.x, v1.y);
        r.w = packh(v1.z, v1.w);
        *(uint4*)(o + i) = r;
    }
}

__global__ void transpose_f16(const float* __restrict__ in, __half* __restrict__ o,
                              int R, int C) {
    __shared__ float t[32][33];
    int c = blockIdx.x * 32 + threadIdx.x;
    #pragma unroll
    for (int i = 0; i < 4; i++) {
        int r = blockIdx.y * 32 + threadIdx.y + i * 8;
        if (r < R && c < C) t[threadIdx.y + i * 8][threadIdx.x] = in[(size_t)r * C + c];
    }
    __syncthreads();
    int rr = blockIdx.y * 32 + threadIdx.x;
    #pragma unroll
    for (int i = 0; i < 4; i++) {
        int cc = blockIdx.x * 32 + threadIdx.y + i * 8;
        if (rr < R && cc < C)
            o[(size_t)cc * R + rr] = __float2half_rn(t[threadIdx.x][threadIdx.y + i * 8]);
    }
}

// out = LN(a + r) * g + be.  Warp-per-row (D=256 -> 8 fp32/lane), shuffle-only.
// Block 256 = 8 rows. No smem, no __syncthreads.
__global__ void add_ln(const float* __restrict__ a, const float* __restrict__ r,
                       const float* __restrict__ g, const float* __restrict__ be,
                       float* __restrict__ out, __half* __restrict__ of) {
    const int lane = threadIdx.x & 31;
    const size_t row = (size_t)blockIdx.x * 8 + (threadIdx.x >> 5);
    const size_t base = row * DD + lane * 8;

    float4 va0 = *(const float4*)(a + base);
    float4 va1 = *(const float4*)(a + base + 4);
    float4 vr0 = *(const float4*)(r + base);
    float4 vr1 = *(const float4*)(r + base + 4);
    float v[8] = {va0.x + vr0.x, va0.y + vr0.y, va0.z + vr0.z, va0.w + vr0.w,
                  va1.x + vr1.x, va1.y + vr1.y, va1.z + vr1.z, va1.w + vr1.w};

    float s = 0.f;
    #pragma unroll
    for (int i = 0; i < 8; i++) s += v[i];
    #pragma unroll
    for (int o = 16; o > 0; o >>= 1) s += __shfl_xor_sync(0xffffffffu, s, o);
    const float mean = s * (1.0f / 256.0f);

    float q = 0.f;
    #pragma unroll
    for (int i = 0; i < 8; i++) {
        v[i] -= mean;
        q += v[i] * v[i];
    }
    #pragma unroll
    for (int o = 16; o > 0; o >>= 1) q += __shfl_xor_sync(0xffffffffu, q, o);
    const float inv = rsqrtf(q * (1.0f / 256.0f) + 1e-5f);

    float4 vg0 = *(const float4*)(g + lane * 8);
    float4 vg1 = *(const float4*)(g + lane * 8 + 4);
    float4 vb0 = *(const float4*)(be + lane * 8);
    float4 vb1 = *(const float4*)(be + lane * 8 + 4);
    float res[8];
    res[0] = v[0] * inv * vg0.x + vb0.x;
    res[1] = v[1] * inv * vg0.y + vb0.y;
    res[2] = v[2] * inv * vg0.z + vb0.z;
    res[3] = v[3] * inv * vg0.w + vb0.w;
    res[4] = v[4] * inv * vg1.x + vb1.x;
    res[5] = v[5] * inv * vg1.y + vb1.y;
    res[6] = v[6] * inv * vg1.z + vb1.z;
    res[7] = v[7] * inv * vg1.w + vb1.w;

    *(float4*)(out + base)     = make_float4(res[0], res[1], res[2], res[3]);
    *(float4*)(out + base + 4) = make_float4(res[4], res[5], res[6], res[7]);
    if (of) {
        uint4 hv;
        hv.x = packh(res[0], res[1]);
        hv.y = packh(res[2], res[3]);
        hv.z = packh(res[4], res[5]);
        hv.w = packh(res[6], res[7]);
        *(uint4*)(of + base) = hv;
    }
}

// ---------------------------------------------------------------------------
// Launch
// ---------------------------------------------------------------------------
extern "C" void kernel_launch(void* const* d_in, const int* in_sizes, int n_in,
                              void* d_out, int out_size) {
    const float* x      = (const float*)d_in[0];
    const float* gamma1 = (const float*)d_in[1];
    const float* beta1  = (const float*)d_in[2];
    const float* W1     = (const float*)d_in[3];
    const float* b1     = (const float*)d_in[4];
    const float* W2     = (const float*)d_in[5];
    const float* b2     = (const float*)d_in[6];
    const float* gamma2 = (const float*)d_in[7];
    const float* beta2  = (const float*)d_in[8];
    float* out = (float*)d_out;

    float *a, *h, *f2;
    __half *xh, *hf, *f1f, *w1t, *w2t;
    cudaGetSymbolAddress((void**)&xh, g_xh);
    cudaGetSymbolAddress((void**)&a, g_a);
    cudaGetSymbolAddress((void**)&h, g_h);
    cudaGetSymbolAddress((void**)&hf, g_hf);
    cudaGetSymbolAddress((void**)&f1f, g_f1f);
    cudaGetSymbolAddress((void**)&f2, g_f2);
    cudaGetSymbolAddress((void**)&w1t, g_w1t);
    cudaGetSymbolAddress((void**)&w2t, g_w2t);

    const int SMEM = 2 * Bb;   // 65536
    cudaFuncSetAttribute(gemm_ffn<2>, cudaFuncAttributeMaxDynamicSharedMemorySize, SMEM);
    cudaFuncSetAttribute(gemm_ffn<3>, cudaFuncAttributeMaxDynamicSharedMemorySize, SMEM);
    cudaFuncSetAttribute(flash_attn, cudaFuncAttributeMaxDynamicSharedMemorySize, FA_SMEM);

    const int rows = BB * SS;

    // conversions
    conv_f16<<<(BB * SS * DD / 8 + 255) / 256, 256>>>(x, xh, (size_t)BB * SS * DD);
    transpose_f16<<<dim3(HH / 32, DD / 32), dim3(32, 8)>>>(W1, w1t, DD, HH);
    transpose_f16<<<dim3(DD / 32, HH / 32), dim3(32, 8)>>>(W2, w2t, HH, DD);

    // 1-3) fused attention: a = softmax(scale * x x^T) x
    flash_attn<<<dim3(SS / 64, BB), 128, FA_SMEM>>>(xh, a);

    // 4) h = LN(a + x), also emit h f16
    add_ln<<<rows / 8, 256>>>(a, x, gamma1, beta1, h, hf);

    // 5) f1 = relu(h @ W1 + b1) -> f16
    gemm_ffn<2><<<dim3(HH / 128, rows / 128), 256, SMEM>>>(
        hf, w1t, nullptr, f1f, b1, rows, HH, DD);

    // 6) f2 = f1 @ W2 + b2
    gemm_ffn<3><<<dim3(DD / 128, rows / 128), 256, SMEM>>>(
        f1f, w2t, f2, nullptr, b2, rows, DD, HH);

    // 7) out = LN(f2 + h)
    add_ln<<<rows / 8, 256>>>(f2, h, gamma2, beta2, out, nullptr);
}

// round 12
// speedup vs baseline: 1.2183x; 1.0444x over previous
#include <cuda_runtime.h>
#include <cuda_fp16.h>
#include <cstdint>
#include <math.h>

#define BB 4
#define SS 4096
#define DD 256
#define HH 1024
// SCALE * log2(e): softmax computed in base-2 domain
#define SCL2E 0.25505654911f

// ---------------------------------------------------------------------------
// Scratch (__device__ globals; no cudaMalloc allowed)
// ---------------------------------------------------------------------------
__device__ __half g_xh[(size_t)BB * SS * DD];
__device__ float  g_h[(size_t)BB * SS * DD];
__device__ __half g_hf[(size_t)BB * SS * DD];
__device__ __half g_f1f[(size_t)BB * SS * HH];
__device__ float  g_f2[(size_t)BB * SS * DD];
__device__ __half g_w1t[(size_t)HH * DD];            // W1^T [H,D] fp16
__device__ __half g_w2t[(size_t)DD * HH];            // W2^T [D,H] fp16

// ---------------------------------------------------------------------------
// Helpers (baseline PTX only: cp.async, ldmatrix, mma.sync)
// ---------------------------------------------------------------------------
__device__ __forceinline__ uint32_t smem_u32(const void* p) {
    uint32_t a;
    asm("{ .reg .u64 t; cvta.to.shared.u64 t, %1; cvt.u32.u64 %0, t; }" : "=r"(a) : "l"(p));
    return a;
}
__device__ __forceinline__ void cpa16(uint32_t d, const void* g) {
    asm volatile("cp.async.cg.shared.global [%0], [%1], 16;" :: "r"(d), "l"(g) : "memory");
}
__device__ __forceinline__ uint32_t swz(uint32_t off) { return off ^ ((off >> 3) & 0x70); }

// Swizzle for 512B rows (256 fp16)
__device__ __forceinline__ uint32_t SWX(int row, int c) {
    return (uint32_t)(row * 512 + ((c ^ (row & 7)) << 4));
}
__device__ __forceinline__ float ex2f(float x) {
    float y;
    asm("ex2.approx.f32 %0, %1;" : "=f"(y) : "f"(x));
    return y;
}

__device__ __forceinline__ void ldsm4(uint32_t& r0, uint32_t& r1, uint32_t& r2, uint32_t& r3,
                                      uint32_t addr) {
    asm volatile("ldmatrix.sync.aligned.m8n8.x4.shared.b16 {%0,%1,%2,%3}, [%4];"
        : "=r"(r0), "=r"(r1), "=r"(r2), "=r"(r3) : "r"(addr));
}
__device__ __forceinline__ void ldsm4t(uint32_t& r0, uint32_t& r1, uint32_t& r2, uint32_t& r3,
                                       uint32_t addr) {
    asm volatile("ldmatrix.sync.aligned.m8n8.x4.trans.shared.b16 {%0,%1,%2,%3}, [%4];"
        : "=r"(r0), "=r"(r1), "=r"(r2), "=r"(r3) : "r"(addr));
}
__device__ __forceinline__ void mma_f16(float* d, uint32_t a0, uint32_t a1, uint32_t a2,
                                        uint32_t a3, uint32_t b0, uint32_t b1) {
    asm volatile("mma.sync.aligned.m16n8k16.row.col.f32.f16.f16.f32 "
        "{%0,%1,%2,%3}, {%4,%5,%6,%7}, {%8,%9}, {%0,%1,%2,%3};"
        : "+f"(d[0]), "+f"(d[1]), "+f"(d[2]), "+f"(d[3])
        : "r"(a0), "r"(a1), "r"(a2), "r"(a3), "r"(b0), "r"(b1));
}
__device__ __forceinline__ uint32_t packh(float a, float b) {
    __half2 h = __floats2half2_rn(a, b);
    return *(uint32_t*)&h;
}

// ---------------------------------------------------------------------------
// Flash attention + fused LN1 (pure fp16 QK/PV, fp32 accum):
//   h[b,q,:] = LN( softmax(scale * x_q . x_k) @ x  +  x[q] ) ; also emit hf (fp16)
// CTA: 64 query rows, 128 threads (4 warps x 16 rows), 2 CTAs/SM.
// K-tile: 64 keys, double-buffered (prefetch before wait).
// smem: Q 32K | K buf0 32K | K buf1 32K = 96K.
// ---------------------------------------------------------------------------
#define FA_SMEM 98304

__global__ void __launch_bounds__(128, 2) flash_attn(
    const __half* __restrict__ xh, const float* __restrict__ x,
    const float* __restrict__ gamma1, const float* __restrict__ beta1,
    float* __restrict__ hout, __half* __restrict__ hfout)
{
    extern __shared__ char smem[];
    const uint32_t sb = smem_u32(smem);
    const int tid = threadIdx.x, wid = tid >> 5, lane = tid & 31;
    const int m0 = blockIdx.x * 64;
    const int bz = blockIdx.y;
    const __half* qp = xh + ((size_t)bz * SS + m0) * DD;
    const __half* kp_all = xh + (size_t)bz * SS * DD;
    const uint32_t QH = sb, KB = sb + 32768;

    // Load Q (64 rows x 512B)
    #pragma unroll
    for (int i = 0; i < 16; i++) {
        int j = tid + i * 128;
        int row = j >> 5, c = j & 31;
        cpa16(QH + SWX(row, c), qp + row * DD + c * 8);
    }
    asm volatile("cp.async.commit_group;" ::: "memory");

    auto load_kv = [&](int t) {
        const uint32_t b = KB + (t & 1) * 32768;
        const __half* kp = kp_all + (size_t)t * 64 * DD;
        #pragma unroll
        for (int i = 0; i < 16; i++) {
            int j = tid + i * 128;
            int row = j >> 5, c = j & 31;
            cpa16(b + SWX(row, c), kp + row * DD + c * 8);
        }
        asm volatile("cp.async.commit_group;" ::: "memory");
    };

    load_kv(0);

    float O[32][4];
    #pragma unroll
    for (int n = 0; n < 32; n++)
        #pragma unroll
        for (int q = 0; q < 4; q++) O[n][q] = 0.0f;
    float m0r = -INFINITY, m1r = -INFINITY, l0 = 0.0f, l1 = 0.0f;

    const int qrow = wid * 16 + (lane & 15);
    const int qc_h = lane >> 4;
    const int krow = ((lane >> 4) << 3) + (lane & 7);
    const int kc_h = (lane >> 3) & 1;
    const int vrow = ((lane >> 3) & 1) * 8 + (lane & 7);

    const int T = SS / 64;   // 64 key-tiles
    for (int t = 0; t < T; t++) {
        // Prefetch next K tile into the other buffer BEFORE waiting on this one.
        if (t + 1 < T) {
            load_kv(t + 1);
            asm volatile("cp.async.wait_group 1;" ::: "memory");
        } else {
            asm volatile("cp.async.wait_group 0;" ::: "memory");
        }
        __syncthreads();
        const uint32_t KH = KB + (t & 1) * 32768;

        // ---- S2 = (scale*log2e) * Q K^T  (log2-domain scores) ----
        float sa[8][4];
        #pragma unroll
        for (int j = 0; j < 8; j++)
            #pragma unroll
            for (int q = 0; q < 4; q++) sa[j][q] = 0.0f;

        #pragma unroll
        for (int s = 0; s < 16; s++) {
            uint32_t ah[4], bh[8][2];
            ldsm4(ah[0], ah[1], ah[2], ah[3], QH + SWX(qrow, 2 * s + qc_h));
            #pragma unroll
            for (int r4 = 0; r4 < 4; r4++) {
                uint32_t off = SWX(krow + 16 * r4, 2 * s + kc_h);
                ldsm4(bh[2 * r4][0], bh[2 * r4][1], bh[2 * r4 + 1][0], bh[2 * r4 + 1][1],
                      KH + off);
            }
            #pragma unroll
            for (int j = 0; j < 8; j++)
                mma_f16(sa[j], ah[0], ah[1], ah[2], ah[3], bh[j][0], bh[j][1]);
        }
        #pragma unroll
        for (int j = 0; j < 8; j++)
            #pragma unroll
            for (int q = 0; q < 4; q++) sa[j][q] *= SCL2E;

        // ---- online softmax in base-2 (rows lane>>2 and +8) ----
        float mx0 = -INFINITY, mx1 = -INFINITY;
        #pragma unroll
        for (int j = 0; j < 8; j++) {
            mx0 = fmaxf(mx0, fmaxf(sa[j][0], sa[j][1]));
            mx1 = fmaxf(mx1, fmaxf(sa[j][2], sa[j][3]));
        }
        mx0 = fmaxf(mx0, __shfl_xor_sync(0xffffffffu, mx0, 1));
        mx0 = fmaxf(mx0, __shfl_xor_sync(0xffffffffu, mx0, 2));
        mx1 = fmaxf(mx1, __shfl_xor_sync(0xffffffffu, mx1, 1));
        mx1 = fmaxf(mx1, __shfl_xor_sync(0xffffffffu, mx1, 2));
        float mn0 = fmaxf(m0r, mx0), mn1 = fmaxf(m1r, mx1);
        float sc0 = ex2f(m0r - mn0), sc1 = ex2f(m1r - mn1);
        m0r = mn0; m1r = mn1;

        float ts0 = 0.0f, ts1 = 0.0f;
        #pragma unroll
        for (int j = 0; j < 8; j++) {
            sa[j][0] = ex2f(sa[j][0] - mn0);
            sa[j][1] = ex2f(sa[j][1] - mn0);
            sa[j][2] = ex2f(sa[j][2] - mn1);
            sa[j][3] = ex2f(sa[j][3] - mn1);
            ts0 += sa[j][0] + sa[j][1];
            ts1 += sa[j][2] + sa[j][3];
        }
        ts0 += __shfl_xor_sync(0xffffffffu, ts0, 1);
        ts0 += __shfl_xor_sync(0xffffffffu, ts0, 2);
        ts1 += __shfl_xor_sync(0xffffffffu, ts1, 1);
        ts1 += __shfl_xor_sync(0xffffffffu, ts1, 2);
        l0 = l0 * sc0 + ts0;
        l1 = l1 * sc1 + ts1;
        if (sc0 != 1.0f || sc1 != 1.0f) {
            #pragma unroll
            for (int n = 0; n < 32; n++) {
                O[n][0] *= sc0; O[n][1] *= sc0;
                O[n][2] *= sc1; O[n][3] *= sc1;
            }
        }

        // ---- P fragments (fp16), 4 k16 chunks over 64 keys ----
        uint32_t pa[4][4];
        #pragma unroll
        for (int ks = 0; ks < 4; ks++) {
            int j0 = 2 * ks, j1 = 2 * ks + 1;
            pa[ks][0] = packh(sa[j0][0], sa[j0][1]);
            pa[ks][1] = packh(sa[j0][2], sa[j0][3]);
            pa[ks][2] = packh(sa[j1][0], sa[j1][1]);
            pa[ks][3] = packh(sa[j1][2], sa[j1][3]);
        }

        // ---- O += P @ V  (V = K tile via ldmatrix.trans) ----
        #pragma unroll
        for (int ks = 0; ks < 4; ks++) {
            #pragma unroll
            for (int g = 0; g < 16; g++) {
                uint32_t v0, v1, v2, v3;
                ldsm4t(v0, v1, v2, v3, KH + SWX(ks * 16 + vrow, 2 * g + (lane >> 4)));
                mma_f16(O[2 * g],     pa[ks][0], pa[ks][1], pa[ks][2], pa[ks][3], v0, v1);
                mma_f16(O[2 * g + 1], pa[ks][0], pa[ks][1], pa[ks][2], pa[ks][3], v2, v3);
            }
        }
        __syncthreads();
    }

    // ---- epilogue: v = O/l + x ; LN1 in-register (row owned by one quad) ----
    const float i0 = 1.0f / l0, i1 = 1.0f / l1;
    const int r0 = lane >> 2, cq = (lane & 3) * 2;
    const size_t rowA = (size_t)bz * SS + m0 + wid * 16 + r0;
    const size_t rowB = rowA + 8;
    const float* xr0 = x + rowA * DD;
    const float* xr1 = x + rowB * DD;

    float s1A = 0.f, s2A = 0.f, s1B = 0.f, s2B = 0.f;
    #pragma unroll
    for (int n = 0; n < 32; n++) {
        const int col = n * 8 + cq;
        float2 xa = *(const float2*)(xr0 + col);
        float2 xb = *(const float2*)(xr1 + col);
        O[n][0] = O[n][0] * i0 + xa.x;
        O[n][1] = O[n][1] * i0 + xa.y;
        O[n][2] = O[n][2] * i1 + xb.x;
        O[n][3] = O[n][3] * i1 + xb.y;
        s1A += O[n][0] + O[n][1];
        s2A += O[n][0] * O[n][0] + O[n][1] * O[n][1];
        s1B += O[n][2] + O[n][3];
        s2B += O[n][2] * O[n][2] + O[n][3] * O[n][3];
    }
    s1A += __shfl_xor_sync(0xffffffffu, s1A, 1);
    s1A += __shfl_xor_sync(0xffffffffu, s1A, 2);
    s2A += __shfl_xor_sync(0xffffffffu, s2A, 1);
    s2A += __shfl_xor_sync(0xffffffffu, s2A, 2);
    s1B += __shfl_xor_sync(0xffffffffu, s1B, 1);
    s1B += __shfl_xor_sync(0xffffffffu, s1B, 2);
    s2B += __shfl_xor_sync(0xffffffffu, s2B, 1);
    s2B += __shfl_xor_sync(0xffffffffu, s2B, 2);

    const float mA = s1A * (1.0f / 256.0f);
    const float vA = s2A * (1.0f / 256.0f) - mA * mA;
    const float invA = rsqrtf(vA + 1e-5f);
    const float mB = s1B * (1.0f / 256.0f);
    const float vB = s2B * (1.0f / 256.0f) - mB * mB;
    const float invB = rsqrtf(vB + 1e-5f);

    float* h0 = hout + rowA * DD;
    float* h1 = hout + rowB * DD;
    __half* hf0 = hfout + rowA * DD;
    __half* hf1 = hfout + rowB * DD;
    #pragma unroll
    for (int n = 0; n < 32; n++) {
        const int col = n * 8 + cq;
        float2 gg = *(const float2*)(gamma1 + col);
        float2 bb = *(const float2*)(beta1 + col);
        float a0 = (O[n][0] - mA) * invA * gg.x + bb.x;
        float a1 = (O[n][1] - mA) * invA * gg.y + bb.y;
        float b0 = (O[n][2] - mB) * invB * gg.x + bb.x;
        float b1 = (O[n][3] - mB) * invB * gg.y + bb.y;
        *(float2*)(h0 + col) = make_float2(a0, a1);
        *(float2*)(h1 + col) = make_float2(b0, b1);
        *(uint32_t*)(hf0 + col) = packh(a0, a1);
        *(uint32_t*)(hf1 + col) = packh(b0, b1);
    }
}

// ---------------------------------------------------------------------------
// FFN GEMM (fp16, 1-term): C[M,N] = A[M,K] * B[N,K]^T
// MODE 2: Cf f16 = relu(acc + bias)      MODE 3: C fp32 = acc + bias
// Block 128x128, K-tile 64, 8 warps (2x4), double-buffered, 2 CTAs/SM.
// ---------------------------------------------------------------------------
#define Bb 32768   // per-buffer: A 16K | B 16K
template <int MODE>
__global__ void __launch_bounds__(256, 2) gemm_ffn(
    const __half* __restrict__ A, const __half* __restrict__ B,
    float* __restrict__ C, __half* __restrict__ Cf,
    const float* __restrict__ bias, int M, int N, int K)
{
    extern __shared__ char smem[];
    const uint32_t sb = smem_u32(smem);
    const int tid = threadIdx.x, wid = tid >> 5, lane = tid & 31;
    const int m0 = blockIdx.y * 128, n0 = blockIdx.x * 128;

    const int wm = wid & 1;
    const int wn = wid >> 1;
    const int a_row = lane & 15, a_kh = lane >> 4;
    const int b_roff = ((lane >> 4) & 1) * 8 + (lane & 7), b_kh = (lane >> 3) & 1;

    float acc[4][4][4];
    #pragma unroll
    for (int i = 0; i < 4; i++)
        #pragma unroll
        for (int j = 0; j < 4; j++)
            #pragma unroll
            for (int q = 0; q < 4; q++) acc[i][j][q] = 0.0f;

    const int KT = K >> 6;

    auto load_tile = [&](int kt) {
        const uint32_t tb = sb + (kt & 1) * Bb;
        const int k0 = kt << 6;
        #pragma unroll
        for (int t = 0; t < 4; t++) {
            int id = tid + t * 256;
            int row = id >> 3, ch = id & 7;
            uint32_t so = swz((uint32_t)(row * 128 + ch * 16));
            cpa16(tb + so,         A + (size_t)(m0 + row) * K + k0 + ch * 8);
            cpa16(tb + 16384 + so, B + (size_t)(n0 + row) * K + k0 + ch * 8);
        }
        asm volatile("cp.async.commit_group;" ::: "memory");
    };

    load_tile(0);

    for (int kt = 0; kt < KT; kt++) {
        if (kt + 1 < KT) {
            load_tile(kt + 1);
            asm volatile("cp.async.wait_group 1;" ::: "memory");
        } else {
            asm volatile("cp.async.wait_group 0;" ::: "memory");
        }
        __syncthreads();

        const uint32_t tb = sb + (kt & 1) * Bb;
        #pragma unroll
        for (int s = 0; s < 4; s++) {
            uint32_t av[4][4];
            #pragma unroll
            for (int i = 0; i < 4; i++) {
                uint32_t off = swz((uint32_t)((wm * 64 + i * 16 + a_row) * 128 +
                                              (s * 2 + a_kh) * 16));
                ldsm4(av[i][0], av[i][1], av[i][2], av[i][3], tb + off);
            }
            uint32_t bv[4][2];
            #pragma unroll
            for (int jj = 0; jj < 2; jj++) {
                uint32_t off = swz((uint32_t)((wn * 32 + jj * 16 + b_roff) * 128 +
                                              (s * 2 + b_kh) * 16));
                ldsm4(bv[2 * jj][0], bv[2 * jj][1], bv[2 * jj + 1][0], bv[2 * jj + 1][1],
                      tb + 16384 + off);
            }
            #pragma unroll
            for (int i = 0; i < 4; i++)
                #pragma unroll
                for (int j = 0; j < 4; j++)
                    mma_f16(acc[i][j], av[i][0], av[i][1], av[i][2], av[i][3],
                            bv[j][0], bv[j][1]);
        }
        __syncthreads();
    }

    const int g = lane >> 2, cq = (lane & 3) * 2;
    #pragma unroll
    for (int i = 0; i < 4; i++) {
        #pragma unroll
        for (int j = 0; j < 4; j++) {
            const int row = m0 + wm * 64 + i * 16 + g;
            const int col = n0 + wn * 32 + j * 8 + cq;
            float v0 = acc[i][j][0], v1 = acc[i][j][1];
            float v2 = acc[i][j][2], v3 = acc[i][j][3];
            const float bv0 = bias[col], bv1 = bias[col + 1];
            v0 += bv0; v1 += bv1; v2 += bv0; v3 += bv1;
            size_t i0 = (size_t)row * N + col;
            size_t i1 = (size_t)(row + 8) * N + col;
            if (MODE == 2) {
                v0 = fmaxf(v0, 0.f); v1 = fmaxf(v1, 0.f);
                v2 = fmaxf(v2, 0.f); v3 = fmaxf(v3, 0.f);
                *(__half2*)(Cf + i0) = __floats2half2_rn(v0, v1);
                *(__half2*)(Cf + i1) = __floats2half2_rn(v2, v3);
            } else {
                *(float2*)(C + i0) = {v0, v1};
                *(float2*)(C + i1) = {v2, v3};
            }
        }
    }
}

// ---------------------------------------------------------------------------
// Elementwise / conversion kernels
// ---------------------------------------------------------------------------
__global__ void conv_f16(const float* __restrict__ in, __half* __restrict__ o, size_t n) {
    size_t i = ((size_t)blockIdx.x * blockDim.x + threadIdx.x) * 8;
    if (i < n) {
        float4 v0 = *(const float4*)(in + i);
        float4 v1 = *(const float4*)(in + i + 4);
        uint4 r;
        r.x = packh(v0.x, v0.y);
        r.y = packh(v0.z, v0.w);
        r.z = packh(v1.x, v1.y);
        r.w = packh(v1.z, v1.w);
        *(uint4*)(o + i) = r;
    }
}

__global__ void transpose_f16(const float* __restrict__ in, __half* __restrict__ o,
                              int R, int C) {
    __shared__ float t[32][33];
    int c = blockIdx.x * 32 + threadIdx.x;
    #pragma unroll
    for (int i = 0; i < 4; i++) {
        int r = blockIdx.y * 32 + threadIdx.y + i * 8;
        if (r < R && c < C) t[threadIdx.y + i * 8][threadIdx.x] = in[(size_t)r * C + c];
    }
    __syncthreads();
    int rr = blockIdx.y * 32 + threadIdx.x;
    #pragma unroll
    for (int i = 0; i < 4; i++) {
        int cc = blockIdx.x * 32 + threadIdx.y + i * 8;
        if (rr < R && cc < C)
            o[(size_t)cc * R + rr] = __float2half_rn(t[threadIdx.x][threadIdx.y + i * 8]);
    }
}

// out = LN(a + r) * g + be.  Warp-per-row (D=256 -> 8 fp32/lane), shuffle-only.
__global__ void add_ln(const float* __restrict__ a, const float* __restrict__ r,
                       const float* __restrict__ g, const float* __restrict__ be,
                       float* __restrict__ out, __half* __restrict__ of) {
    const int lane = threadIdx.x & 31;
    const size_t row = (size_t)blockIdx.x * 8 + (threadIdx.x >> 5);
    const size_t base = row * DD + lane * 8;

    float4 va0 = *(const float4*)(a + base);
    float4 va1 = *(const float4*)(a + base + 4);
    float4 vr0 = *(const float4*)(r + base);
    float4 vr1 = *(const float4*)(r + base + 4);
    float v[8] = {va0.x + vr0.x, va0.y + vr0.y, va0.z + vr0.z, va0.w + vr0.w,
                  va1.x + vr1.x, va1.y + vr1.y, va1.z + vr1.z, va1.w + vr1.w};

    float s = 0.f;
    #pragma unroll
    for (int i = 0; i < 8; i++) s += v[i];
    #pragma unroll
    for (int o = 16; o > 0; o >>= 1) s += __shfl_xor_sync(0xffffffffu, s, o);
    const float mean = s * (1.0f / 256.0f);

    float q = 0.f;
    #pragma unroll
    for (int i = 0; i < 8; i++) {
        v[i] -= mean;
        q += v[i] * v[i];
    }
    #pragma unroll
    for (int o = 16; o > 0; o >>= 1) q += __shfl_xor_sync(0xffffffffu, q, o);
    const float inv = rsqrtf(q * (1.0f / 256.0f) + 1e-5f);

    float4 vg0 = *(const float4*)(g + lane * 8);
    float4 vg1 = *(const float4*)(g + lane * 8 + 4);
    float4 vb0 = *(const float4*)(be + lane * 8);
    float4 vb1 = *(const float4*)(be + lane * 8 + 4);
    float res[8];
    res[0] = v[0] * inv * vg0.x + vb0.x;
    res[1] = v[1] * inv * vg0.y + vb0.y;
    res[2] = v[2] * inv * vg0.z + vb0.z;
    res[3] = v[3] * inv * vg0.w + vb0.w;
    res[4] = v[4] * inv * vg1.x + vb1.x;
    res[5] = v[5] * inv * vg1.y + vb1.y;
    res[6] = v[6] * inv * vg1.z + vb1.z;
    res[7] = v[7] * inv * vg1.w + vb1.w;

    *(float4*)(out + base)     = make_float4(res[0], res[1], res[2], res[3]);
    *(float4*)(out + base + 4) = make_float4(res[4], res[5], res[6], res[7]);
    if (of) {
        uint4 hv;
        hv.x = packh(res[0], res[1]);
        hv.y = packh(res[2], res[3]);
        hv.z = packh(res[4], res[5]);
        hv.w = packh(res[6], res[7]);
        *(uint4*)(of + base) = hv;
    }
}

// ---------------------------------------------------------------------------
// Launch
// ---------------------------------------------------------------------------
extern "C" void kernel_launch(void* const* d_in, const int* in_sizes, int n_in,
                              void* d_out, int out_size) {
    const float* x      = (const float*)d_in[0];
    const float* gamma1 = (const float*)d_in[1];
    const float* beta1  = (const float*)d_in[2];
    const float* W1     = (const float*)d_in[3];
    const float* b1     = (const float*)d_in[4];
    const float* W2     = (const float*)d_in[5];
    const float* b2     = (const float*)d_in[6];
    const float* gamma2 = (const float*)d_in[7];
    const float* beta2  = (const float*)d_in[8];
    float* out = (float*)d_out;

    float *h, *f2;
    __half *xh, *hf, *f1f, *w1t, *w2t;
    cudaGetSymbolAddress((void**)&xh, g_xh);
    cudaGetSymbolAddress((void**)&h, g_h);
    cudaGetSymbolAddress((void**)&hf, g_hf);
    cudaGetSymbolAddress((void**)&f1f, g_f1f);
    cudaGetSymbolAddress((void**)&f2, g_f2);
    cudaGetSymbolAddress((void**)&w1t, g_w1t);
    cudaGetSymbolAddress((void**)&w2t, g_w2t);

    const int SMEM = 2 * Bb;   // 65536
    cudaFuncSetAttribute(gemm_ffn<2>, cudaFuncAttributeMaxDynamicSharedMemorySize, SMEM);
    cudaFuncSetAttribute(gemm_ffn<3>, cudaFuncAttributeMaxDynamicSharedMemorySize, SMEM);
    cudaFuncSetAttribute(flash_attn, cudaFuncAttributeMaxDynamicSharedMemorySize, FA_SMEM);

    const int rows = BB * SS;

    // conversions
    conv_f16<<<(BB * SS * DD / 8 + 255) / 256, 256>>>(x, xh, (size_t)BB * SS * DD);
    transpose_f16<<<dim3(HH / 32, DD / 32), dim3(32, 8)>>>(W1, w1t, DD, HH);
    transpose_f16<<<dim3(DD / 32, HH / 32), dim3(32, 8)>>>(W2, w2t, HH, DD);

    // 1-4) fused attention + LN1: h = LN(softmax(scale x x^T) x + x), hf = f16(h)
    flash_attn<<<dim3(SS / 64, BB), 128, FA_SMEM>>>(xh, x, gamma1, beta1, h, hf);

    // 5) f1 = relu(h @ W1 + b1) -> f16
    gemm_ffn<2><<<dim3(HH / 128, rows / 128), 256, SMEM>>>(
        hf, w1t, nullptr, f1f, b1, rows, HH, DD);

    // 6) f2 = f1 @ W2 + b2
    gemm_ffn<3><<<dim3(DD / 128, rows / 128), 256, SMEM>>>(
        f1f, w2t, f2, nullptr, b2, rows, DD, HH);

    // 7) out = LN(f2 + h)
    add_ln<<<rows / 8, 256>>>(f2, h, gamma2, beta2, out, nullptr);
}